// round 13
// baseline (speedup 1.0000x reference)
#include <cuda_runtime.h>
#include <cuda_fp16.h>
#include <cstdint>

#define SQ 512
#define NB 64
#define NH 1024
#define NI 256
#define NG 4096
#define HSEQ ((size_t)SQ*NB*NH)

// scratch (no allocations allowed)
__device__ float    g_xg[(size_t)SQ*NB*NG];   // xg = x@Wx + bx + bh (fp32)
__device__ uint4    g_hfrag[(size_t)SQ*8192]; // h in fp16 A-fragment order, 64MB
__device__ unsigned g_flags[8*SQ];            // per-(group,step) arrival counters

__device__ __forceinline__ unsigned tf32u(float x){
  unsigned u; asm("cvt.rna.tf32.f32 %0, %1;" : "=r"(u) : "f"(x)); return u;
}
__device__ __forceinline__ float tf32f(float x){ return __uint_as_float(tf32u(x)); }
__device__ __forceinline__ void mma8(float d[4], unsigned a0,unsigned a1,unsigned a2,unsigned a3,
                                     unsigned b0,unsigned b1){
  asm("mma.sync.aligned.m16n8k8.row.col.f32.tf32.tf32.f32 "
      "{%0,%1,%2,%3},{%4,%5,%6,%7},{%8,%9},{%0,%1,%2,%3};"
      : "+f"(d[0]),"+f"(d[1]),"+f"(d[2]),"+f"(d[3])
      : "r"(a0),"r"(a1),"r"(a2),"r"(a3),"r"(b0),"r"(b1));
}
__device__ __forceinline__ void mma16(float d[4], unsigned a0,unsigned a1,unsigned a2,unsigned a3,
                                      unsigned b0,unsigned b1){
  asm("mma.sync.aligned.m16n8k16.row.col.f32.f16.f16.f32 "
      "{%0,%1,%2,%3},{%4,%5,%6,%7},{%8,%9},{%0,%1,%2,%3};"
      : "+f"(d[0]),"+f"(d[1]),"+f"(d[2]),"+f"(d[3])
      : "r"(a0),"r"(a1),"r"(a2),"r"(a3),"r"(b0),"r"(b1));
}
__device__ __forceinline__ unsigned packh2(float lo, float hi){
  __half2 h = __floats2half2_rn(lo, hi);
  return *reinterpret_cast<unsigned*>(&h);
}
__device__ __forceinline__ float sigf(float x){ return 1.f/(1.f+__expf(-x)); }

// ---------------------------------------------------------------------------
// Phase 1: xg[m][gate*1024+j] = x[m,:] @ Wgate[:, j] + bx + bh  (tf32 MMA)
// CTA tile 256(M) x 128(N), K=256 in 8 chunks of 32. 512 thr, 16 warps =
// 4(m) x 4(n), warp tile 64x32. Grid (32,128): halves L2 tile traffic vs
// the old 128x64 tiling. Block (0,0) re-zeroes the recurrence sync flags.
// ---------------------------------------------------------------------------
__global__ void __launch_bounds__(512) xg_gemm(
    const float* __restrict__ x,
    const float* __restrict__ Wa,const float* __restrict__ Wb,
    const float* __restrict__ Wc,const float* __restrict__ Wd,
    const float* __restrict__ xa,const float* __restrict__ xb,
    const float* __restrict__ xc,const float* __restrict__ xd,
    const float* __restrict__ ha,const float* __restrict__ hb,
    const float* __restrict__ hc,const float* __restrict__ hd)
{
  extern __shared__ float smx[];
  float* As   = smx;            // 256*36 = 9216 floats
  float* Bs   = smx + 9216;     // 32*136 = 4352 floats
  float* bias = smx + 13568;    // 128 floats
  const int tid=threadIdx.x, w=tid>>5, lane=tid&31;
  const int g=lane>>2, tg=lane&3, wm=w>>2, wn=w&3;
  const int mbase=blockIdx.y*256, nb=blockIdx.x*128;
  const int gate=nb>>10, colbase=nb&1023;

  if (blockIdx.x==0 && blockIdx.y==0){           // flag reset for lstm_rec
    #pragma unroll
    for(int p=0;p<8;p++) g_flags[tid+p*512]=0u;
  }

  const float* Wg = gate==0?Wa:gate==1?Wb:gate==2?Wc:Wd;
  const float* bx = gate==0?xa:gate==1?xb:gate==2?xc:xd;
  const float* bh = gate==0?ha:gate==1?hb:gate==2?hc:hd;
  if (tid<128) bias[tid]=bx[colbase+tid]+bh[colbase+tid];

  float acc[4][4][4];
  #pragma unroll
  for(int i=0;i<4;i++)
    #pragma unroll
    for(int j=0;j<4;j++)
      #pragma unroll
      for(int e=0;e<4;e++) acc[i][j][e]=0.f;

  for(int kc=0;kc<8;kc++){
    #pragma unroll
    for(int p=0;p<4;p++){       // stage A: 256 rows x 32 k (tf32)
      int fid=tid+p*512, row=fid>>3, c4=(fid&7)*4;
      float4 v=*(const float4*)(x+(size_t)(mbase+row)*NI+kc*32+c4);
      v.x=tf32f(v.x); v.y=tf32f(v.y); v.z=tf32f(v.z); v.w=tf32f(v.w);
      *(float4*)(As+row*36+c4)=v;
    }
    #pragma unroll
    for(int p=0;p<2;p++){       // stage B: 32 k x 128 cols (tf32)
      int fid=tid+p*512, r=fid>>5, c4=(fid&31)*4;
      float4 v=*(const float4*)(Wg+(size_t)(kc*32+r)*NH+colbase+c4);
      v.x=tf32f(v.x); v.y=tf32f(v.y); v.z=tf32f(v.z); v.w=tf32f(v.w);
      *(float4*)(Bs+r*136+c4)=v;
    }
    __syncthreads();
    #pragma unroll
    for(int kk=0;kk<4;kk++){
      unsigned a[4][4];
      #pragma unroll
      for(int mt=0;mt<4;mt++){
        int ar=wm*64+mt*16+g, k0=kk*8+tg;
        a[mt][0]=__float_as_uint(As[ar*36+k0]);
        a[mt][1]=__float_as_uint(As[(ar+8)*36+k0]);
        a[mt][2]=__float_as_uint(As[ar*36+k0+4]);
        a[mt][3]=__float_as_uint(As[(ar+8)*36+k0+4]);
      }
      #pragma unroll
      for(int nt=0;nt<4;nt++){
        int nc=wn*32+nt*8+g, k0=kk*8+tg;
        unsigned b0=__float_as_uint(Bs[k0*136+nc]);
        unsigned b1=__float_as_uint(Bs[(k0+4)*136+nc]);
        #pragma unroll
        for(int mt=0;mt<4;mt++)
          mma8(acc[mt][nt],a[mt][0],a[mt][1],a[mt][2],a[mt][3],b0,b1);
      }
    }
    __syncthreads();
  }
  #pragma unroll
  for(int mt=0;mt<4;mt++){
    #pragma unroll
    for(int nt=0;nt<4;nt++){
      int row0=mbase+wm*64+mt*16+g;
      int colL=wn*32+nt*8+2*tg;
      float b0v=bias[colL], b1v=bias[colL+1];
      float* o0=g_xg+(size_t)row0*NG+nb+colL;
      *(float2*)o0               = make_float2(acc[mt][nt][0]+b0v, acc[mt][nt][1]+b1v);
      *(float2*)(o0+(size_t)8*NG)= make_float2(acc[mt][nt][2]+b0v, acc[mt][nt][3]+b1v);
    }
  }
}

// ---------------------------------------------------------------------------
// Phase 2: persistent recurrence in fp16 MMA (m16n8k16), fp32 accum/state.
// 128 CTAs (1/SM), 256 threads (8 warps). CTA c owns h-cols [8c,8c+8) and the
// matching 8 cols of all 4 gates. Chunk16 j = h-cols [16j,16j+16).
//  - h exchanged via g_hfrag (fp16 A-fragments); producers' (2tg,2tg+1)
//    column pairs pack directly (no transpose); consumers __ldcg into MMA A.
//  - B (Wh fp16 fragments) live in REGISTERS (16 uint4/warp, loaded once):
//    zero B traffic in the mainloop.
//  - warp w (=kh slab) computes the FULL 64x32 tile over chunk16s [8w,8w+8):
//    per j: 4 LDG.128 (A) + 16 MMA, double-buffered.
//  - 8-way kh reduction via red, SINGLE buffer (64KB): safe because a warp
//    writes red at step t+1 only after passing flag[t], which its own CTA's
//    epilogue released only after finishing its red reads.
//  - sync: 8 producer groups of 16 CTAs; 4 epilogue warps arrive via
//    red.release.gpu.add (target 64); consumer warp w tight-polls group w
//    with ld.acquire (poll period ~ L2 RTT). Poll (<64): stale-safe.
// ---------------------------------------------------------------------------
__global__ void __launch_bounds__(256,1) lstm_rec(
    const float* __restrict__ Wh1,const float* __restrict__ Wh2,
    const float* __restrict__ Wh3,const float* __restrict__ Wh4,
    float* __restrict__ out)
{
  extern __shared__ float sm[];
  float4* red4 = (float4*)sm;             // 4096 float4 (64KB): kh partials
  uint4*  Bp4  = (uint4*)(sm + 16384);    // 4096 uint4 (64KB): B pack (init only)

  const int tid=threadIdx.x, w=tid>>5, lane=tid&31;
  const int g=lane>>2, tg=lane&3, cta=blockIdx.x;

  { // one-time fp16 B pack: Bp4[(j*2+p)*32+lane] = {b0,b1 gate 2p, b0,b1 gate 2p+1}
    const float* Whs[4]={Wh1,Wh2,Wh3,Wh4};
    for(int idx=tid; idx<4096; idx+=256){
      int ln=idx&31, p=(idx>>5)&1, j=idx>>6;
      int g_=ln>>2, tg_=ln&3;
      int col=8*cta+g_;
      int k0=16*j+2*tg_;
      uint4 val;
      const float* W0=Whs[2*p];
      const float* W1=Whs[2*p+1];
      val.x=packh2(W0[(size_t)k0*NH+col],     W0[(size_t)(k0+1)*NH+col]);
      val.y=packh2(W0[(size_t)(k0+8)*NH+col], W0[(size_t)(k0+9)*NH+col]);
      val.z=packh2(W1[(size_t)k0*NH+col],     W1[(size_t)(k0+1)*NH+col]);
      val.w=packh2(W1[(size_t)(k0+8)*NH+col], W1[(size_t)(k0+9)*NH+col]);
      Bp4[(j*2+p)*32+ln]=val;
    }
  }
  __syncthreads();

  uint4 Breg[16];                          // warp's B frags -> registers
  #pragma unroll
  for(int jj=0;jj<8;jj++){
    Breg[2*jj]   = Bp4[((w*8+jj)*2+0)*32+lane];
    Breg[2*jj+1] = Bp4[((w*8+jj)*2+1)*32+lane];
  }
  __syncthreads();                         // Bp4 dead beyond this point

  unsigned* myArr = g_flags + (cta>>4)*SQ;   // producer arrival row (16-CTA group)
  unsigned* myPol = g_flags + w*SQ;          // consumer poll row (slab w)
  float cst[4]={0,0,0,0}, hv[4]={0,0,0,0};

  #pragma unroll 1
  for(int t=0;t<SQ;t++){
    // xg loads: independent of h -> issue before any waiting (epilogue warps)
    float2 xr[8];
    if(w<4){
      const float* xb = g_xg + ((size_t)t*NB + 16*w + g)*NG + 8*cta + 2*tg;
      #pragma unroll
      for(int nt=0;nt<4;nt++){
        xr[nt]   = __ldcg((const float2*)(xb + nt*NH));
        xr[4+nt] = __ldcg((const float2*)(xb + (size_t)8*NG + nt*NH));
      }
    }

    float acc[4][4][4];
    #pragma unroll
    for(int m=0;m<4;m++)
      #pragma unroll
      for(int n=0;n<4;n++)
        #pragma unroll
        for(int e=0;e<4;e++) acc[m][n][e]=0.f;

    if(t>0){
      { // tight per-warp acquire poll on this slab's producer group
        const unsigned* fp = myPol + (t-1);
        unsigned v;
        do {
          asm volatile("ld.acquire.gpu.global.u32 %0, [%1];" : "=r"(v) : "l"(fp) : "memory");
        } while(v < 64u);
      }
      const uint4* fb = g_hfrag + (size_t)(t-1)*8192;
      uint4 A[2][4];
      { int j=w*8;
        #pragma unroll
        for(int m=0;m<4;m++) A[0][m]=__ldcg(fb + ((j*4+m)*32+lane));
      }
      #pragma unroll
      for(int jj=0;jj<8;jj++){
        int cur=jj&1, nxt=cur^1;
        if(jj<7){
          int j=w*8+jj+1;
          #pragma unroll
          for(int m=0;m<4;m++) A[nxt][m]=__ldcg(fb + ((j*4+m)*32+lane));
        }
        #pragma unroll
        for(int m=0;m<4;m++){
          mma16(acc[m][0],A[cur][m].x,A[cur][m].y,A[cur][m].z,A[cur][m].w,Breg[2*jj].x,Breg[2*jj].y);
          mma16(acc[m][1],A[cur][m].x,A[cur][m].y,A[cur][m].z,A[cur][m].w,Breg[2*jj].z,Breg[2*jj].w);
          mma16(acc[m][2],A[cur][m].x,A[cur][m].y,A[cur][m].z,A[cur][m].w,Breg[2*jj+1].x,Breg[2*jj+1].y);
          mma16(acc[m][3],A[cur][m].x,A[cur][m].y,A[cur][m].z,A[cur][m].w,Breg[2*jj+1].z,Breg[2*jj+1].w);
        }
      }
    }

    #pragma unroll
    for(int m=0;m<4;m++)                  // every warp writes its slab
      #pragma unroll
      for(int n=0;n<4;n++)
        red4[((w*16+m*4+n)*32+lane)] =
          make_float4(acc[m][n][0],acc[m][n][1],acc[m][n][2],acc[m][n][3]);
    __syncthreads();                      // the ONE barrier: red ready
    if(w<4){
      float ga[4][4];
      #pragma unroll
      for(int n=0;n<4;n++)
        #pragma unroll
        for(int e=0;e<4;e++) ga[n][e]=0.f;
      #pragma unroll
      for(int s=0;s<8;s++)
        #pragma unroll
        for(int n=0;n<4;n++){
          float4 u=red4[((s*16+w*4+n)*32+lane)];
          ga[n][0]+=u.x; ga[n][1]+=u.y; ga[n][2]+=u.z; ga[n][3]+=u.w;
        }
      // gates: nt order = f,i,o,cand; e: 0=(r0,c0) 1=(r0,c1) 2=(r1,c0) 3=(r1,c1)
      float gv[4][4];
      #pragma unroll
      for(int n=0;n<4;n++){
        gv[n][0]=ga[n][0]+xr[n].x;   gv[n][1]=ga[n][1]+xr[n].y;
        gv[n][2]=ga[n][2]+xr[4+n].x; gv[n][3]=ga[n][3]+xr[4+n].y;
      }
      #pragma unroll
      for(int e=0;e<4;e++){
        float f=sigf(gv[0][e]), ii=sigf(gv[1][e]);
        float o=sigf(gv[2][e]), cd=tanhf(gv[3][e]);
        cst[e]=f*cst[e]+ii*cd;
        hv[e]=o*tanhf(cst[e]);
      }
      // fragment store FIRST (cross-CTA dependency), then arrive
      unsigned p0=packh2(hv[0],hv[1]), p1=packh2(hv[2],hv[3]);
      uint2* fw = ((uint2*)(g_hfrag + (size_t)t*8192))
                  + (((cta>>1)*4 + w)*32 + lane)*2 + (cta&1);
      *fw = make_uint2(p0,p1);
      __syncwarp();                       // intra-warp ordering of frag STGs
      if(lane==0){                        // cumulative release arrival (+1)
        unsigned* fp = myArr + t;
        asm volatile("red.release.gpu.global.add.u32 [%0], %1;"
                     :: "l"(fp), "r"(1u) : "memory");
      }
      // h_seq output store (fp32), off the release path
      float* hw = out + ((size_t)t*NB + 16*w + g)*NH + 8*cta + 2*tg;
      *(float2*)hw                = make_float2(hv[0],hv[1]);
      *(float2*)(hw+(size_t)8*NH) = make_float2(hv[2],hv[3]);
    }
  }

  if(w<4){  // tails: h_final (== h_seq[511]) then c_final
    float* ho = out + HSEQ + (size_t)(16*w+g)*NH + 8*cta + 2*tg;
    float* co = ho + (size_t)NB*NH;
    *(float2*)ho                = make_float2(hv[0],hv[1]);
    *(float2*)(ho+(size_t)8*NH) = make_float2(hv[2],hv[3]);
    *(float2*)co                = make_float2(cst[0],cst[1]);
    *(float2*)(co+(size_t)8*NH) = make_float2(cst[2],cst[3]);
  }
}

extern "C" void kernel_launch(void* const* d_in, const int* in_sizes, int n_in,
                              void* d_out, int out_size){
  const float* x =(const float*)d_in[0];
  const float* W1=(const float*)d_in[1];  const float* b1=(const float*)d_in[2];
  const float* W2=(const float*)d_in[3];  const float* b2=(const float*)d_in[4];
  const float* W3=(const float*)d_in[5];  const float* b3=(const float*)d_in[6];
  const float* W4=(const float*)d_in[7];  const float* b4=(const float*)d_in[8];
  const float* W5=(const float*)d_in[9];  const float* b5=(const float*)d_in[10];
  const float* W6=(const float*)d_in[11]; const float* b6=(const float*)d_in[12];
  const float* W7=(const float*)d_in[13]; const float* b7=(const float*)d_in[14];
  const float* W8=(const float*)d_in[15]; const float* b8=(const float*)d_in[16];
  float* out=(float*)d_out;

  cudaFuncSetAttribute(xg_gemm,  cudaFuncAttributeMaxDynamicSharedMemorySize, 55296);
  cudaFuncSetAttribute(lstm_rec, cudaFuncAttributeMaxDynamicSharedMemorySize, 131072);

  dim3 grid(32,128);
  xg_gemm<<<grid,512,55296>>>(x, W1,W3,W5,W7, b1,b3,b5,b7, b2,b4,b6,b8);
  lstm_rec<<<128,256,131072>>>(W2,W4,W6,W8, out);
}

// round 14
// speedup vs baseline: 1.4274x; 1.4274x over previous
#include <cuda_runtime.h>
#include <cuda_fp16.h>
#include <cstdint>

#define SQ 512
#define NB 64
#define NH 1024
#define NI 256
#define NG 4096
#define HSEQ ((size_t)SQ*NB*NH)

// scratch (no allocations allowed)
__device__ float    g_xg[(size_t)SQ*NB*NG];   // xg = x@Wx + bx + bh (fp32)
__device__ uint4    g_hfrag[(size_t)SQ*8192]; // h in fp16 A-fragment order, 64MB
__device__ unsigned g_flags[8*SQ];            // per-(group,step) arrival counters

__device__ __forceinline__ unsigned tf32u(float x){
  unsigned u; asm("cvt.rna.tf32.f32 %0, %1;" : "=r"(u) : "f"(x)); return u;
}
__device__ __forceinline__ float tf32f(float x){ return __uint_as_float(tf32u(x)); }
__device__ __forceinline__ void mma8(float d[4], unsigned a0,unsigned a1,unsigned a2,unsigned a3,
                                     unsigned b0,unsigned b1){
  asm("mma.sync.aligned.m16n8k8.row.col.f32.tf32.tf32.f32 "
      "{%0,%1,%2,%3},{%4,%5,%6,%7},{%8,%9},{%0,%1,%2,%3};"
      : "+f"(d[0]),"+f"(d[1]),"+f"(d[2]),"+f"(d[3])
      : "r"(a0),"r"(a1),"r"(a2),"r"(a3),"r"(b0),"r"(b1));
}
__device__ __forceinline__ void mma16(float d[4], unsigned a0,unsigned a1,unsigned a2,unsigned a3,
                                      unsigned b0,unsigned b1){
  asm("mma.sync.aligned.m16n8k16.row.col.f32.f16.f16.f32 "
      "{%0,%1,%2,%3},{%4,%5,%6,%7},{%8,%9},{%0,%1,%2,%3};"
      : "+f"(d[0]),"+f"(d[1]),"+f"(d[2]),"+f"(d[3])
      : "r"(a0),"r"(a1),"r"(a2),"r"(a3),"r"(b0),"r"(b1));
}
__device__ __forceinline__ unsigned packh2(float lo, float hi){
  __half2 h = __floats2half2_rn(lo, hi);
  return *reinterpret_cast<unsigned*>(&h);
}
__device__ __forceinline__ float sigf(float x){ return 1.f/(1.f+__expf(-x)); }

// ---------------------------------------------------------------------------
// Phase 1: xg[m][gate*1024+j] = x[m,:] @ Wgate[:, j] + bx + bh  (tf32 MMA)
// CTA tile 256(M) x 128(N), K=256 in 8 chunks of 32. 512 thr, 16 warps =
// 4(m) x 4(n), warp tile 64x32. Grid (32,128): halves L2 tile traffic vs
// the old 128x64 tiling. Block (0,0) re-zeroes the recurrence sync flags.
// ---------------------------------------------------------------------------
__global__ void __launch_bounds__(512) xg_gemm(
    const float* __restrict__ x,
    const float* __restrict__ Wa,const float* __restrict__ Wb,
    const float* __restrict__ Wc,const float* __restrict__ Wd,
    const float* __restrict__ xa,const float* __restrict__ xb,
    const float* __restrict__ xc,const float* __restrict__ xd,
    const float* __restrict__ ha,const float* __restrict__ hb,
    const float* __restrict__ hc,const float* __restrict__ hd)
{
  extern __shared__ float smx[];
  float* As   = smx;            // 256*36 = 9216 floats
  float* Bs   = smx + 9216;     // 32*136 = 4352 floats
  float* bias = smx + 13568;    // 128 floats
  const int tid=threadIdx.x, w=tid>>5, lane=tid&31;
  const int g=lane>>2, tg=lane&3, wm=w>>2, wn=w&3;
  const int mbase=blockIdx.y*256, nb=blockIdx.x*128;
  const int gate=nb>>10, colbase=nb&1023;

  if (blockIdx.x==0 && blockIdx.y==0){           // flag reset for lstm_rec
    #pragma unroll
    for(int p=0;p<8;p++) g_flags[tid+p*512]=0u;
  }

  const float* Wg = gate==0?Wa:gate==1?Wb:gate==2?Wc:Wd;
  const float* bx = gate==0?xa:gate==1?xb:gate==2?xc:xd;
  const float* bh = gate==0?ha:gate==1?hb:gate==2?hc:hd;
  if (tid<128) bias[tid]=bx[colbase+tid]+bh[colbase+tid];

  float acc[4][4][4];
  #pragma unroll
  for(int i=0;i<4;i++)
    #pragma unroll
    for(int j=0;j<4;j++)
      #pragma unroll
      for(int e=0;e<4;e++) acc[i][j][e]=0.f;

  for(int kc=0;kc<8;kc++){
    #pragma unroll
    for(int p=0;p<4;p++){       // stage A: 256 rows x 32 k (tf32)
      int fid=tid+p*512, row=fid>>3, c4=(fid&7)*4;
      float4 v=*(const float4*)(x+(size_t)(mbase+row)*NI+kc*32+c4);
      v.x=tf32f(v.x); v.y=tf32f(v.y); v.z=tf32f(v.z); v.w=tf32f(v.w);
      *(float4*)(As+row*36+c4)=v;
    }
    #pragma unroll
    for(int p=0;p<2;p++){       // stage B: 32 k x 128 cols (tf32)
      int fid=tid+p*512, r=fid>>5, c4=(fid&31)*4;
      float4 v=*(const float4*)(Wg+(size_t)(kc*32+r)*NH+colbase+c4);
      v.x=tf32f(v.x); v.y=tf32f(v.y); v.z=tf32f(v.z); v.w=tf32f(v.w);
      *(float4*)(Bs+r*136+c4)=v;
    }
    __syncthreads();
    #pragma unroll
    for(int kk=0;kk<4;kk++){
      unsigned a[4][4];
      #pragma unroll
      for(int mt=0;mt<4;mt++){
        int ar=wm*64+mt*16+g, k0=kk*8+tg;
        a[mt][0]=__float_as_uint(As[ar*36+k0]);
        a[mt][1]=__float_as_uint(As[(ar+8)*36+k0]);
        a[mt][2]=__float_as_uint(As[ar*36+k0+4]);
        a[mt][3]=__float_as_uint(As[(ar+8)*36+k0+4]);
      }
      #pragma unroll
      for(int nt=0;nt<4;nt++){
        int nc=wn*32+nt*8+g, k0=kk*8+tg;
        unsigned b0=__float_as_uint(Bs[k0*136+nc]);
        unsigned b1=__float_as_uint(Bs[(k0+4)*136+nc]);
        #pragma unroll
        for(int mt=0;mt<4;mt++)
          mma8(acc[mt][nt],a[mt][0],a[mt][1],a[mt][2],a[mt][3],b0,b1);
      }
    }
    __syncthreads();
  }
  #pragma unroll
  for(int mt=0;mt<4;mt++){
    #pragma unroll
    for(int nt=0;nt<4;nt++){
      int row0=mbase+wm*64+mt*16+g;
      int colL=wn*32+nt*8+2*tg;
      float b0v=bias[colL], b1v=bias[colL+1];
      float* o0=g_xg+(size_t)row0*NG+nb+colL;
      *(float2*)o0               = make_float2(acc[mt][nt][0]+b0v, acc[mt][nt][1]+b1v);
      *(float2*)(o0+(size_t)8*NG)= make_float2(acc[mt][nt][2]+b0v, acc[mt][nt][3]+b1v);
    }
  }
}

// ---------------------------------------------------------------------------
// Phase 2: persistent recurrence in fp16 MMA (m16n8k16), fp32 accum/state.
// (Exact R11 configuration -- the 2861us baseline: B frags in smem, parity-
// buffered red, nanosleep poll.)
// 128 CTAs (1/SM), 256 threads (8 warps). CTA c owns h-cols [8c,8c+8) and the
// matching 8 cols of all 4 gates. Chunk16 j = h-cols [16j,16j+16).
//  - h exchanged via g_hfrag (fp16 A-fragments); producers' (2tg,2tg+1)
//    column pairs pack directly (no transpose); consumers __ldcg into MMA A.
//  - warp w (=kh slab, 8 slabs) computes the FULL 64x32 tile over chunk16s
//    j in [8w,8w+8): per j: 4 LDG.128 (A, all mt) + 2 LDS.128 (B, all gates)
//    + 16 MMA. B (Wh fp16, packed in smem Bp 64KB) read exactly once.
//  - 8-way kh reduction via red (2x64KB, t-parity); epilogue on warps 0-3;
//    ONE __syncthreads per step.
//  - sync: 8 producer groups (CTAs 16G..16G+16) own flag g_flags[G*SQ+t];
//    4 epilogue warps/CTA arrive with red.release.gpu.add -> target 64.
//    Consumer warp w acquire-polls group w. Poll uses (<64): stale-safe.
// ---------------------------------------------------------------------------
__global__ void __launch_bounds__(256,1) lstm_rec(
    const float* __restrict__ Wh1,const float* __restrict__ Wh2,
    const float* __restrict__ Wh3,const float* __restrict__ Wh4,
    float* __restrict__ out)
{
  extern __shared__ float sm[];
  uint4*  Bp4  = (uint4*)sm;              // 4096 uint4 (64KB): packed fp16 B frags
  float4* red4 = (float4*)(sm + 16384);   // 2 x 4096 float4 (128KB): kh partials

  const int tid=threadIdx.x, w=tid>>5, lane=tid&31;
  const int g=lane>>2, tg=lane&3, cta=blockIdx.x;

  { // one-time fp16 B pack: Bp4[(j*2+p)*32+lane] = {b0,b1 of gate 2p, b0,b1 of 2p+1}
    const float* Whs[4]={Wh1,Wh2,Wh3,Wh4};
    for(int idx=tid; idx<4096; idx+=256){
      int ln=idx&31, p=(idx>>5)&1, j=idx>>6;
      int g_=ln>>2, tg_=ln&3;
      int col=8*cta+g_;
      int k0=16*j+2*tg_;
      uint4 val;
      const float* W0=Whs[2*p];
      const float* W1=Whs[2*p+1];
      val.x=packh2(W0[(size_t)k0*NH+col],     W0[(size_t)(k0+1)*NH+col]);
      val.y=packh2(W0[(size_t)(k0+8)*NH+col], W0[(size_t)(k0+9)*NH+col]);
      val.z=packh2(W1[(size_t)k0*NH+col],     W1[(size_t)(k0+1)*NH+col]);
      val.w=packh2(W1[(size_t)(k0+8)*NH+col], W1[(size_t)(k0+9)*NH+col]);
      Bp4[(j*2+p)*32+ln]=val;
    }
  }
  __syncthreads();

  unsigned* myArr = g_flags + (cta>>4)*SQ;   // producer arrival row (16-CTA group)
  unsigned* myPol = g_flags + w*SQ;          // consumer poll row (slab w)
  float cst[4]={0,0,0,0}, hv[4]={0,0,0,0};

  #pragma unroll 1
  for(int t=0;t<SQ;t++){
    // xg loads: independent of h -> issue before any waiting (epilogue warps)
    float2 xr[8];
    if(w<4){
      const float* xb = g_xg + ((size_t)t*NB + 16*w + g)*NG + 8*cta + 2*tg;
      #pragma unroll
      for(int nt=0;nt<4;nt++){
        xr[nt]   = __ldcg((const float2*)(xb + nt*NH));
        xr[4+nt] = __ldcg((const float2*)(xb + (size_t)8*NG + nt*NH));
      }
    }

    float acc[4][4][4];
    #pragma unroll
    for(int m=0;m<4;m++)
      #pragma unroll
      for(int n=0;n<4;n++)
        #pragma unroll
        for(int e=0;e<4;e++) acc[m][n][e]=0.f;

    if(t>0){
      { // per-warp acquire poll on this slab's producer group (converged)
        const unsigned* fp = myPol + (t-1);
        unsigned v;
        asm volatile("ld.acquire.gpu.global.u32 %0, [%1];" : "=r"(v) : "l"(fp) : "memory");
        while(v < 64u){
          __nanosleep(20);
          asm volatile("ld.acquire.gpu.global.u32 %0, [%1];" : "=r"(v) : "l"(fp) : "memory");
        }
      }
      const uint4* fb = g_hfrag + (size_t)(t-1)*8192;
      uint4 A[2][4], B0[2], B1[2];
      { int j=w*8;
        #pragma unroll
        for(int m=0;m<4;m++) A[0][m]=__ldcg(fb + ((j*4+m)*32+lane));
        B0[0]=Bp4[(j*2+0)*32+lane]; B1[0]=Bp4[(j*2+1)*32+lane];
      }
      #pragma unroll
      for(int jj=0;jj<8;jj++){
        int cur=jj&1, nxt=cur^1;
        if(jj<7){
          int j=w*8+jj+1;
          #pragma unroll
          for(int m=0;m<4;m++) A[nxt][m]=__ldcg(fb + ((j*4+m)*32+lane));
          B0[nxt]=Bp4[(j*2+0)*32+lane]; B1[nxt]=Bp4[(j*2+1)*32+lane];
        }
        #pragma unroll
        for(int m=0;m<4;m++){
          mma16(acc[m][0],A[cur][m].x,A[cur][m].y,A[cur][m].z,A[cur][m].w,B0[cur].x,B0[cur].y);
          mma16(acc[m][1],A[cur][m].x,A[cur][m].y,A[cur][m].z,A[cur][m].w,B0[cur].z,B0[cur].w);
          mma16(acc[m][2],A[cur][m].x,A[cur][m].y,A[cur][m].z,A[cur][m].w,B1[cur].x,B1[cur].y);
          mma16(acc[m][3],A[cur][m].x,A[cur][m].y,A[cur][m].z,A[cur][m].w,B1[cur].z,B1[cur].w);
        }
      }
    }

    float4* rb = red4 + (t&1)*4096;
    #pragma unroll
    for(int m=0;m<4;m++)                  // every warp writes its slab
      #pragma unroll
      for(int n=0;n<4;n++)
        rb[((w*16+m*4+n)*32+lane)] =
          make_float4(acc[m][n][0],acc[m][n][1],acc[m][n][2],acc[m][n][3]);
    __syncthreads();                      // the ONE barrier: red ready
    if(w<4){
      float ga[4][4];
      #pragma unroll
      for(int n=0;n<4;n++)
        #pragma unroll
        for(int e=0;e<4;e++) ga[n][e]=0.f;
      #pragma unroll
      for(int s=0;s<8;s++)
        #pragma unroll
        for(int n=0;n<4;n++){
          float4 u=rb[((s*16+w*4+n)*32+lane)];
          ga[n][0]+=u.x; ga[n][1]+=u.y; ga[n][2]+=u.z; ga[n][3]+=u.w;
        }
      // gates: nt order = f,i,o,cand; e: 0=(r0,c0) 1=(r0,c1) 2=(r1,c0) 3=(r1,c1)
      float gv[4][4];
      #pragma unroll
      for(int n=0;n<4;n++){
        gv[n][0]=ga[n][0]+xr[n].x;   gv[n][1]=ga[n][1]+xr[n].y;
        gv[n][2]=ga[n][2]+xr[4+n].x; gv[n][3]=ga[n][3]+xr[4+n].y;
      }
      #pragma unroll
      for(int e=0;e<4;e++){
        float f=sigf(gv[0][e]), ii=sigf(gv[1][e]);
        float o=sigf(gv[2][e]), cd=tanhf(gv[3][e]);
        cst[e]=f*cst[e]+ii*cd;
        hv[e]=o*tanhf(cst[e]);
      }
      // fragment store FIRST (cross-CTA dependency), then arrive
      unsigned p0=packh2(hv[0],hv[1]), p1=packh2(hv[2],hv[3]);
      uint2* fw = ((uint2*)(g_hfrag + (size_t)t*8192))
                  + (((cta>>1)*4 + w)*32 + lane)*2 + (cta&1);
      *fw = make_uint2(p0,p1);
      __syncwarp();                       // intra-warp ordering of frag STGs
      if(lane==0){                        // cumulative release arrival (+1)
        unsigned* fp = myArr + t;
        asm volatile("red.release.gpu.global.add.u32 [%0], %1;"
                     :: "l"(fp), "r"(1u) : "memory");
      }
      // h_seq output store (fp32), off the release path
      float* hw = out + ((size_t)t*NB + 16*w + g)*NH + 8*cta + 2*tg;
      *(float2*)hw                = make_float2(hv[0],hv[1]);
      *(float2*)(hw+(size_t)8*NH) = make_float2(hv[2],hv[3]);
    }
  }

  if(w<4){  // tails: h_final (== h_seq[511]) then c_final
    float* ho = out + HSEQ + (size_t)(16*w+g)*NH + 8*cta + 2*tg;
    float* co = ho + (size_t)NB*NH;
    *(float2*)ho                = make_float2(hv[0],hv[1]);
    *(float2*)(ho+(size_t)8*NH) = make_float2(hv[2],hv[3]);
    *(float2*)co                = make_float2(cst[0],cst[1]);
    *(float2*)(co+(size_t)8*NH) = make_float2(cst[2],cst[3]);
  }
}

extern "C" void kernel_launch(void* const* d_in, const int* in_sizes, int n_in,
                              void* d_out, int out_size){
  const float* x =(const float*)d_in[0];
  const float* W1=(const float*)d_in[1];  const float* b1=(const float*)d_in[2];
  const float* W2=(const float*)d_in[3];  const float* b2=(const float*)d_in[4];
  const float* W3=(const float*)d_in[5];  const float* b3=(const float*)d_in[6];
  const float* W4=(const float*)d_in[7];  const float* b4=(const float*)d_in[8];
  const float* W5=(const float*)d_in[9];  const float* b5=(const float*)d_in[10];
  const float* W6=(const float*)d_in[11]; const float* b6=(const float*)d_in[12];
  const float* W7=(const float*)d_in[13]; const float* b7=(const float*)d_in[14];
  const float* W8=(const float*)d_in[15]; const float* b8=(const float*)d_in[16];
  float* out=(float*)d_out;

  cudaFuncSetAttribute(xg_gemm,  cudaFuncAttributeMaxDynamicSharedMemorySize, 55296);
  cudaFuncSetAttribute(lstm_rec, cudaFuncAttributeMaxDynamicSharedMemorySize, 196608);

  dim3 grid(32,128);
  xg_gemm<<<grid,512,55296>>>(x, W1,W3,W5,W7, b1,b3,b5,b7, b2,b4,b6,b8);
  lstm_rec<<<128,256,196608>>>(W2,W4,W6,W8, out);
}

// round 15
// speedup vs baseline: 1.4656x; 1.0267x over previous
#include <cuda_runtime.h>
#include <cuda_fp16.h>
#include <cstdint>

#define SQ 512
#define NB 64
#define NH 1024
#define NI 256
#define NG 4096
#define HSEQ ((size_t)SQ*NB*NH)

// scratch (no allocations allowed)
__device__ float    g_xg[(size_t)SQ*NB*NG];   // xg = x@Wx + bx + bh (fp32)
__device__ uint4    g_hfrag[(size_t)SQ*8192]; // h in fp16 A-fragment order, 64MB
__device__ unsigned g_flags[8*SQ];            // per-(group,step) arrival counters

__device__ __forceinline__ unsigned tf32u(float x){
  unsigned u; asm("cvt.rna.tf32.f32 %0, %1;" : "=r"(u) : "f"(x)); return u;
}
__device__ __forceinline__ float tf32f(float x){ return __uint_as_float(tf32u(x)); }
__device__ __forceinline__ void mma8(float d[4], unsigned a0,unsigned a1,unsigned a2,unsigned a3,
                                     unsigned b0,unsigned b1){
  asm("mma.sync.aligned.m16n8k8.row.col.f32.tf32.tf32.f32 "
      "{%0,%1,%2,%3},{%4,%5,%6,%7},{%8,%9},{%0,%1,%2,%3};"
      : "+f"(d[0]),"+f"(d[1]),"+f"(d[2]),"+f"(d[3])
      : "r"(a0),"r"(a1),"r"(a2),"r"(a3),"r"(b0),"r"(b1));
}
__device__ __forceinline__ void mma16(float d[4], unsigned a0,unsigned a1,unsigned a2,unsigned a3,
                                      unsigned b0,unsigned b1){
  asm("mma.sync.aligned.m16n8k16.row.col.f32.f16.f16.f32 "
      "{%0,%1,%2,%3},{%4,%5,%6,%7},{%8,%9},{%0,%1,%2,%3};"
      : "+f"(d[0]),"+f"(d[1]),"+f"(d[2]),"+f"(d[3])
      : "r"(a0),"r"(a1),"r"(a2),"r"(a3),"r"(b0),"r"(b1));
}
__device__ __forceinline__ unsigned packh2(float lo, float hi){
  __half2 h = __floats2half2_rn(lo, hi);
  return *reinterpret_cast<unsigned*>(&h);
}
__device__ __forceinline__ float sigf(float x){ return 1.f/(1.f+__expf(-x)); }

// ---------------------------------------------------------------------------
// Phase 1: xg[m][gate*1024+j] = x[m,:] @ Wgate[:, j] + bx + bh  (tf32 MMA)
// CTA tile 256(M) x 128(N), K=256 in 8 chunks of 32. 512 thr, 16 warps =
// 4(m) x 4(n). Block (0,0) re-zeroes the recurrence sync flags.
// ---------------------------------------------------------------------------
__global__ void __launch_bounds__(512) xg_gemm(
    const float* __restrict__ x,
    const float* __restrict__ Wa,const float* __restrict__ Wb,
    const float* __restrict__ Wc,const float* __restrict__ Wd,
    const float* __restrict__ xa,const float* __restrict__ xb,
    const float* __restrict__ xc,const float* __restrict__ xd,
    const float* __restrict__ ha,const float* __restrict__ hb,
    const float* __restrict__ hc,const float* __restrict__ hd)
{
  extern __shared__ float smx[];
  float* As   = smx;            // 256*36 = 9216 floats
  float* Bs   = smx + 9216;     // 32*136 = 4352 floats
  float* bias = smx + 13568;    // 128 floats
  const int tid=threadIdx.x, w=tid>>5, lane=tid&31;
  const int g=lane>>2, tg=lane&3, wm=w>>2, wn=w&3;
  const int mbase=blockIdx.y*256, nb=blockIdx.x*128;
  const int gate=nb>>10, colbase=nb&1023;

  if (blockIdx.x==0 && blockIdx.y==0){           // flag reset for lstm_rec
    #pragma unroll
    for(int p=0;p<8;p++) g_flags[tid+p*512]=0u;
  }

  const float* Wg = gate==0?Wa:gate==1?Wb:gate==2?Wc:Wd;
  const float* bx = gate==0?xa:gate==1?xb:gate==2?xc:xd;
  const float* bh = gate==0?ha:gate==1?hb:gate==2?hc:hd;
  if (tid<128) bias[tid]=bx[colbase+tid]+bh[colbase+tid];

  float acc[4][4][4];
  #pragma unroll
  for(int i=0;i<4;i++)
    #pragma unroll
    for(int j=0;j<4;j++)
      #pragma unroll
      for(int e=0;e<4;e++) acc[i][j][e]=0.f;

  for(int kc=0;kc<8;kc++){
    #pragma unroll
    for(int p=0;p<4;p++){       // stage A: 256 rows x 32 k (tf32)
      int fid=tid+p*512, row=fid>>3, c4=(fid&7)*4;
      float4 v=*(const float4*)(x+(size_t)(mbase+row)*NI+kc*32+c4);
      v.x=tf32f(v.x); v.y=tf32f(v.y); v.z=tf32f(v.z); v.w=tf32f(v.w);
      *(float4*)(As+row*36+c4)=v;
    }
    #pragma unroll
    for(int p=0;p<2;p++){       // stage B: 32 k x 128 cols (tf32)
      int fid=tid+p*512, r=fid>>5, c4=(fid&31)*4;
      float4 v=*(const float4*)(Wg+(size_t)(kc*32+r)*NH+colbase+c4);
      v.x=tf32f(v.x); v.y=tf32f(v.y); v.z=tf32f(v.z); v.w=tf32f(v.w);
      *(float4*)(Bs+r*136+c4)=v;
    }
    __syncthreads();
    #pragma unroll
    for(int kk=0;kk<4;kk++){
      unsigned a[4][4];
      #pragma unroll
      for(int mt=0;mt<4;mt++){
        int ar=wm*64+mt*16+g, k0=kk*8+tg;
        a[mt][0]=__float_as_uint(As[ar*36+k0]);
        a[mt][1]=__float_as_uint(As[(ar+8)*36+k0]);
        a[mt][2]=__float_as_uint(As[ar*36+k0+4]);
        a[mt][3]=__float_as_uint(As[(ar+8)*36+k0+4]);
      }
      #pragma unroll
      for(int nt=0;nt<4;nt++){
        int nc=wn*32+nt*8+g, k0=kk*8+tg;
        unsigned b0=__float_as_uint(Bs[k0*136+nc]);
        unsigned b1=__float_as_uint(Bs[(k0+4)*136+nc]);
        #pragma unroll
        for(int mt=0;mt<4;mt++)
          mma8(acc[mt][nt],a[mt][0],a[mt][1],a[mt][2],a[mt][3],b0,b1);
      }
    }
    __syncthreads();
  }
  #pragma unroll
  for(int mt=0;mt<4;mt++){
    #pragma unroll
    for(int nt=0;nt<4;nt++){
      int row0=mbase+wm*64+mt*16+g;
      int colL=wn*32+nt*8+2*tg;
      float b0v=bias[colL], b1v=bias[colL+1];
      float* o0=g_xg+(size_t)row0*NG+nb+colL;
      *(float2*)o0               = make_float2(acc[mt][nt][0]+b0v, acc[mt][nt][1]+b1v);
      *(float2*)(o0+(size_t)8*NG)= make_float2(acc[mt][nt][2]+b0v, acc[mt][nt][3]+b1v);
    }
  }
}

// ---------------------------------------------------------------------------
// Phase 2: persistent recurrence, fp16 MMA (m16n8k16), fp32 accum/state.
// 128 CTAs (1/SM), 512 threads (16 warps). CTA c owns h-cols [8c,8c+8) and
// the matching 8 cols of all 4 gates. Chunk16 j = h-cols [16j,16j+16).
// Warp w = (kh=w>>1 in 0..7, mh=w&1): slab j in [8kh,8kh+8), m-rows
// [32mh,32mh+32) (mt = 2mh, 2mh+1). Per j: 2 A LDG.128 + 2 B LDS.128 + 8 MMA
// -> 64 MMA/warp/step, 4 warps/SMSP for latency hiding (vs 2 in R13).
//  - h via g_hfrag (fp16 A-frags, [t][j][mt][lane] uint4), producer packs
//    (2tg,2tg+1) column pairs directly; consumers __ldcg into MMA A.
//  - 2-phase kh reduction (R8 pattern): warps 8-15 write slot (kh-4,mh),
//    warps 0-7 add in place, epilogue warps 0-3 sum 4 kh' slots for mt=w.
//    red = 2 x 32KB (t-parity; epilogue(t) reads precede t+2 writes via the
//    two t+1 barriers). Two __syncthreads per step.
//  - sync: 8 producer groups of 16 CTAs; 4 epilogue warps arrive via
//    red.release.gpu.add (target 64); consumer warp polls group kh with
//    ld.acquire + nanosleep. Poll (<64): stale-safe under ncu replay.
// ---------------------------------------------------------------------------
__global__ void __launch_bounds__(512,1) lstm_rec(
    const float* __restrict__ Wh1,const float* __restrict__ Wh2,
    const float* __restrict__ Wh3,const float* __restrict__ Wh4,
    float* __restrict__ out)
{
  extern __shared__ float sm[];
  float4* red4 = (float4*)sm;             // 2 x 2048 float4 (64KB): kh partials
  uint4*  Bp4  = (uint4*)(sm + 16384);    // 4096 uint4 (64KB): packed fp16 B frags

  const int tid=threadIdx.x, w=tid>>5, lane=tid&31;
  const int g=lane>>2, tg=lane&3, cta=blockIdx.x;
  const int kh=w>>1, mh=w&1;

  { // one-time fp16 B pack: Bp4[(j*2+p)*32+lane] = {b0,b1 of gate 2p, b0,b1 of 2p+1}
    const float* Whs[4]={Wh1,Wh2,Wh3,Wh4};
    for(int idx=tid; idx<4096; idx+=512){
      int ln=idx&31, p=(idx>>5)&1, j=idx>>6;
      int g_=ln>>2, tg_=ln&3;
      int col=8*cta+g_;
      int k0=16*j+2*tg_;
      uint4 val;
      const float* W0=Whs[2*p];
      const float* W1=Whs[2*p+1];
      val.x=packh2(W0[(size_t)k0*NH+col],     W0[(size_t)(k0+1)*NH+col]);
      val.y=packh2(W0[(size_t)(k0+8)*NH+col], W0[(size_t)(k0+9)*NH+col]);
      val.z=packh2(W1[(size_t)k0*NH+col],     W1[(size_t)(k0+1)*NH+col]);
      val.w=packh2(W1[(size_t)(k0+8)*NH+col], W1[(size_t)(k0+9)*NH+col]);
      Bp4[(j*2+p)*32+ln]=val;
    }
  }
  __syncthreads();

  unsigned* myArr = g_flags + (cta>>4)*SQ;   // producer arrival row (16-CTA group)
  unsigned* myPol = g_flags + kh*SQ;         // consumer poll row (slab kh)
  float cst[4]={0,0,0,0}, hv[4]={0,0,0,0};

  #pragma unroll 1
  for(int t=0;t<SQ;t++){
    // xg loads: independent of h -> issue before any waiting (epilogue warps)
    float2 xr[8];
    if(w<4){
      const float* xb = g_xg + ((size_t)t*NB + 16*w + g)*NG + 8*cta + 2*tg;
      #pragma unroll
      for(int nt=0;nt<4;nt++){
        xr[nt]   = __ldcg((const float2*)(xb + nt*NH));
        xr[4+nt] = __ldcg((const float2*)(xb + (size_t)8*NG + nt*NH));
      }
    }

    float acc[2][4][4];
    #pragma unroll
    for(int i=0;i<2;i++)
      #pragma unroll
      for(int n=0;n<4;n++)
        #pragma unroll
        for(int e=0;e<4;e++) acc[i][n][e]=0.f;

    if(t>0){
      { // per-warp acquire poll on this slab's producer group (converged)
        const unsigned* fp = myPol + (t-1);
        unsigned v;
        asm volatile("ld.acquire.gpu.global.u32 %0, [%1];" : "=r"(v) : "l"(fp) : "memory");
        while(v < 64u){
          __nanosleep(20);
          asm volatile("ld.acquire.gpu.global.u32 %0, [%1];" : "=r"(v) : "l"(fp) : "memory");
        }
      }
      const uint4* fb = g_hfrag + (size_t)(t-1)*8192;
      uint4 A[2][2];
      { int j=kh*8;
        A[0][0]=__ldcg(fb + ((j*4 + 2*mh+0)*32+lane));
        A[0][1]=__ldcg(fb + ((j*4 + 2*mh+1)*32+lane));
      }
      #pragma unroll
      for(int jj=0;jj<8;jj++){
        int cur=jj&1, nxt=cur^1;
        int j=kh*8+jj;
        if(jj<7){
          A[nxt][0]=__ldcg(fb + (((j+1)*4 + 2*mh+0)*32+lane));
          A[nxt][1]=__ldcg(fb + (((j+1)*4 + 2*mh+1)*32+lane));
        }
        uint4 B0=Bp4[(j*2+0)*32+lane];
        uint4 B1=Bp4[(j*2+1)*32+lane];
        #pragma unroll
        for(int i=0;i<2;i++){
          mma16(acc[i][0],A[cur][i].x,A[cur][i].y,A[cur][i].z,A[cur][i].w,B0.x,B0.y);
          mma16(acc[i][1],A[cur][i].x,A[cur][i].y,A[cur][i].z,A[cur][i].w,B0.z,B0.w);
          mma16(acc[i][2],A[cur][i].x,A[cur][i].y,A[cur][i].z,A[cur][i].w,B1.x,B1.y);
          mma16(acc[i][3],A[cur][i].x,A[cur][i].y,A[cur][i].z,A[cur][i].w,B1.z,B1.w);
        }
      }
    }

    // 2-phase kh reduction. slot s = (kh mod 4)*2 + mh, layout
    // [i(2)][n(4)][lane] float4 -> 8 slots x 8 x 32 = 2048 float4 per buffer.
    float4* rb = red4 + (t&1)*2048;
    if(w>=8){                             // phase A: kh 4..7 write slots
      int s=(kh-4)*2+mh;
      #pragma unroll
      for(int i=0;i<2;i++)
        #pragma unroll
        for(int n=0;n<4;n++)
          rb[((s*8 + i*4+n)*32+lane)] =
            make_float4(acc[i][n][0],acc[i][n][1],acc[i][n][2],acc[i][n][3]);
    }
    __syncthreads();                      // barrier 1: slots written
    if(w<8){                              // phase B: kh 0..3 add in place
      int s=kh*2+mh;
      #pragma unroll
      for(int i=0;i<2;i++)
        #pragma unroll
        for(int n=0;n<4;n++){
          float4 u=rb[((s*8 + i*4+n)*32+lane)];
          u.x+=acc[i][n][0]; u.y+=acc[i][n][1]; u.z+=acc[i][n][2]; u.w+=acc[i][n][3];
          rb[((s*8 + i*4+n)*32+lane)]=u;
        }
    }
    __syncthreads();                      // barrier 2: folded slots ready
    if(w<4){                              // epilogue: warp w owns mt=w rows
      int mhE=w>>1, ih=w&1;
      float ga[4][4];
      #pragma unroll
      for(int n=0;n<4;n++)
        #pragma unroll
        for(int e=0;e<4;e++) ga[n][e]=0.f;
      #pragma unroll
      for(int k2=0;k2<4;k2++){            // sum 4 folded kh' slots
        int s=k2*2+mhE;
        #pragma unroll
        for(int n=0;n<4;n++){
          float4 u=rb[((s*8 + ih*4+n)*32+lane)];
          ga[n][0]+=u.x; ga[n][1]+=u.y; ga[n][2]+=u.z; ga[n][3]+=u.w;
        }
      }
      // gates: nt order = f,i,o,cand; e: 0=(r0,c0) 1=(r0,c1) 2=(r1,c0) 3=(r1,c1)
      float gv[4][4];
      #pragma unroll
      for(int n=0;n<4;n++){
        gv[n][0]=ga[n][0]+xr[n].x;   gv[n][1]=ga[n][1]+xr[n].y;
        gv[n][2]=ga[n][2]+xr[4+n].x; gv[n][3]=ga[n][3]+xr[4+n].y;
      }
      #pragma unroll
      for(int e=0;e<4;e++){
        float f=sigf(gv[0][e]), ii=sigf(gv[1][e]);
        float o=sigf(gv[2][e]), cd=tanhf(gv[3][e]);
        cst[e]=f*cst[e]+ii*cd;
        hv[e]=o*tanhf(cst[e]);
      }
      // fragment store FIRST (cross-CTA dependency), then arrive
      unsigned p0=packh2(hv[0],hv[1]), p1=packh2(hv[2],hv[3]);
      uint2* fw = ((uint2*)(g_hfrag + (size_t)t*8192))
                  + (((cta>>1)*4 + w)*32 + lane)*2 + (cta&1);
      *fw = make_uint2(p0,p1);
      __syncwarp();                       // intra-warp ordering of frag STGs
      if(lane==0){                        // cumulative release arrival (+1)
        unsigned* fp = myArr + t;
        asm volatile("red.release.gpu.global.add.u32 [%0], %1;"
                     :: "l"(fp), "r"(1u) : "memory");
      }
      // h_seq output store (fp32), off the release path
      float* hw = out + ((size_t)t*NB + 16*w + g)*NH + 8*cta + 2*tg;
      *(float2*)hw                = make_float2(hv[0],hv[1]);
      *(float2*)(hw+(size_t)8*NH) = make_float2(hv[2],hv[3]);
    }
  }

  if(w<4){  // tails: h_final (== h_seq[511]) then c_final
    float* ho = out + HSEQ + (size_t)(16*w+g)*NH + 8*cta + 2*tg;
    float* co = ho + (size_t)NB*NH;
    *(float2*)ho                = make_float2(hv[0],hv[1]);
    *(float2*)(ho+(size_t)8*NH) = make_float2(hv[2],hv[3]);
    *(float2*)co                = make_float2(cst[0],cst[1]);
    *(float2*)(co+(size_t)8*NH) = make_float2(cst[2],cst[3]);
  }
}

extern "C" void kernel_launch(void* const* d_in, const int* in_sizes, int n_in,
                              void* d_out, int out_size){
  const float* x =(const float*)d_in[0];
  const float* W1=(const float*)d_in[1];  const float* b1=(const float*)d_in[2];
  const float* W2=(const float*)d_in[3];  const float* b2=(const float*)d_in[4];
  const float* W3=(const float*)d_in[5];  const float* b3=(const float*)d_in[6];
  const float* W4=(const float*)d_in[7];  const float* b4=(const float*)d_in[8];
  const float* W5=(const float*)d_in[9];  const float* b5=(const float*)d_in[10];
  const float* W6=(const float*)d_in[11]; const float* b6=(const float*)d_in[12];
  const float* W7=(const float*)d_in[13]; const float* b7=(const float*)d_in[14];
  const float* W8=(const float*)d_in[15]; const float* b8=(const float*)d_in[16];
  float* out=(float*)d_out;

  cudaFuncSetAttribute(xg_gemm,  cudaFuncAttributeMaxDynamicSharedMemorySize, 55296);
  cudaFuncSetAttribute(lstm_rec, cudaFuncAttributeMaxDynamicSharedMemorySize, 131072);

  dim3 grid(32,128);
  xg_gemm<<<grid,512,55296>>>(x, W1,W3,W5,W7, b1,b3,b5,b7, b2,b4,b6,b8);
  lstm_rec<<<128,512,131072>>>(W2,W4,W6,W8, out);
}

// round 16
// speedup vs baseline: 1.7270x; 1.1784x over previous
#include <cuda_runtime.h>
#include <cuda_fp16.h>
#include <cstdint>

#define SQ 512
#define NB 64
#define NH 1024
#define NI 256
#define NG 4096
#define HSEQ ((size_t)SQ*NB*NH)

// scratch (no allocations allowed)
__device__ float    g_xg[(size_t)SQ*NB*NG];   // xg = x@Wx + bx + bh (fp32)
__device__ uint4    g_hfrag[(size_t)SQ*8192]; // h in fp16 A-fragment order, 64MB
__device__ unsigned g_flags[8*SQ];            // per-(group,step) arrival counters

__device__ __forceinline__ unsigned tf32u(float x){
  unsigned u; asm("cvt.rna.tf32.f32 %0, %1;" : "=r"(u) : "f"(x)); return u;
}
__device__ __forceinline__ float tf32f(float x){ return __uint_as_float(tf32u(x)); }
__device__ __forceinline__ void mma8(float d[4], unsigned a0,unsigned a1,unsigned a2,unsigned a3,
                                     unsigned b0,unsigned b1){
  asm("mma.sync.aligned.m16n8k8.row.col.f32.tf32.tf32.f32 "
      "{%0,%1,%2,%3},{%4,%5,%6,%7},{%8,%9},{%0,%1,%2,%3};"
      : "+f"(d[0]),"+f"(d[1]),"+f"(d[2]),"+f"(d[3])
      : "r"(a0),"r"(a1),"r"(a2),"r"(a3),"r"(b0),"r"(b1));
}
__device__ __forceinline__ void mma16(float d[4], unsigned a0,unsigned a1,unsigned a2,unsigned a3,
                                      unsigned b0,unsigned b1){
  asm("mma.sync.aligned.m16n8k16.row.col.f32.f16.f16.f32 "
      "{%0,%1,%2,%3},{%4,%5,%6,%7},{%8,%9},{%0,%1,%2,%3};"
      : "+f"(d[0]),"+f"(d[1]),"+f"(d[2]),"+f"(d[3])
      : "r"(a0),"r"(a1),"r"(a2),"r"(a3),"r"(b0),"r"(b1));
}
__device__ __forceinline__ unsigned packh2(float lo, float hi){
  __half2 h = __floats2half2_rn(lo, hi);
  return *reinterpret_cast<unsigned*>(&h);
}
// fast gate math: tanh.approx (sm_75+), sigmoid via tanh identity
__device__ __forceinline__ float tanha(float x){
  float y; asm("tanh.approx.f32 %0, %1;" : "=f"(y) : "f"(x)); return y;
}
__device__ __forceinline__ float sigfa(float x){ return fmaf(0.5f, tanha(0.5f*x), 0.5f); }

// ---------------------------------------------------------------------------
// Phase 1: xg[m][gate*1024+j] = x[m,:] @ Wgate[:, j] + bx + bh  (tf32 MMA)
// CTA tile 256(M) x 128(N), K=256 in 8 chunks of 32. 512 thr, 16 warps =
// 4(m) x 4(n). Block (0,0) re-zeroes the recurrence sync flags.
// ---------------------------------------------------------------------------
__global__ void __launch_bounds__(512) xg_gemm(
    const float* __restrict__ x,
    const float* __restrict__ Wa,const float* __restrict__ Wb,
    const float* __restrict__ Wc,const float* __restrict__ Wd,
    const float* __restrict__ xa,const float* __restrict__ xb,
    const float* __restrict__ xc,const float* __restrict__ xd,
    const float* __restrict__ ha,const float* __restrict__ hb,
    const float* __restrict__ hc,const float* __restrict__ hd)
{
  extern __shared__ float smx[];
  float* As   = smx;            // 256*36 = 9216 floats
  float* Bs   = smx + 9216;     // 32*136 = 4352 floats
  float* bias = smx + 13568;    // 128 floats
  const int tid=threadIdx.x, w=tid>>5, lane=tid&31;
  const int g=lane>>2, tg=lane&3, wm=w>>2, wn=w&3;
  const int mbase=blockIdx.y*256, nb=blockIdx.x*128;
  const int gate=nb>>10, colbase=nb&1023;

  if (blockIdx.x==0 && blockIdx.y==0){           // flag reset for lstm_rec
    #pragma unroll
    for(int p=0;p<8;p++) g_flags[tid+p*512]=0u;
  }

  const float* Wg = gate==0?Wa:gate==1?Wb:gate==2?Wc:Wd;
  const float* bx = gate==0?xa:gate==1?xb:gate==2?xc:xd;
  const float* bh = gate==0?ha:gate==1?hb:gate==2?hc:hd;
  if (tid<128) bias[tid]=bx[colbase+tid]+bh[colbase+tid];

  float acc[4][4][4];
  #pragma unroll
  for(int i=0;i<4;i++)
    #pragma unroll
    for(int j=0;j<4;j++)
      #pragma unroll
      for(int e=0;e<4;e++) acc[i][j][e]=0.f;

  for(int kc=0;kc<8;kc++){
    #pragma unroll
    for(int p=0;p<4;p++){       // stage A: 256 rows x 32 k (tf32)
      int fid=tid+p*512, row=fid>>3, c4=(fid&7)*4;
      float4 v=*(const float4*)(x+(size_t)(mbase+row)*NI+kc*32+c4);
      v.x=tf32f(v.x); v.y=tf32f(v.y); v.z=tf32f(v.z); v.w=tf32f(v.w);
      *(float4*)(As+row*36+c4)=v;
    }
    #pragma unroll
    for(int p=0;p<2;p++){       // stage B: 32 k x 128 cols (tf32)
      int fid=tid+p*512, r=fid>>5, c4=(fid&31)*4;
      float4 v=*(const float4*)(Wg+(size_t)(kc*32+r)*NH+colbase+c4);
      v.x=tf32f(v.x); v.y=tf32f(v.y); v.z=tf32f(v.z); v.w=tf32f(v.w);
      *(float4*)(Bs+r*136+c4)=v;
    }
    __syncthreads();
    #pragma unroll
    for(int kk=0;kk<4;kk++){
      unsigned a[4][4];
      #pragma unroll
      for(int mt=0;mt<4;mt++){
        int ar=wm*64+mt*16+g, k0=kk*8+tg;
        a[mt][0]=__float_as_uint(As[ar*36+k0]);
        a[mt][1]=__float_as_uint(As[(ar+8)*36+k0]);
        a[mt][2]=__float_as_uint(As[ar*36+k0+4]);
        a[mt][3]=__float_as_uint(As[(ar+8)*36+k0+4]);
      }
      #pragma unroll
      for(int nt=0;nt<4;nt++){
        int nc=wn*32+nt*8+g, k0=kk*8+tg;
        unsigned b0=__float_as_uint(Bs[k0*136+nc]);
        unsigned b1=__float_as_uint(Bs[(k0+4)*136+nc]);
        #pragma unroll
        for(int mt=0;mt<4;mt++)
          mma8(acc[mt][nt],a[mt][0],a[mt][1],a[mt][2],a[mt][3],b0,b1);
      }
    }
    __syncthreads();
  }
  #pragma unroll
  for(int mt=0;mt<4;mt++){
    #pragma unroll
    for(int nt=0;nt<4;nt++){
      int row0=mbase+wm*64+mt*16+g;
      int colL=wn*32+nt*8+2*tg;
      float b0v=bias[colL], b1v=bias[colL+1];
      float* o0=g_xg+(size_t)row0*NG+nb+colL;
      *(float2*)o0               = make_float2(acc[mt][nt][0]+b0v, acc[mt][nt][1]+b1v);
      *(float2*)(o0+(size_t)8*NG)= make_float2(acc[mt][nt][2]+b0v, acc[mt][nt][3]+b1v);
    }
  }
}

// ---------------------------------------------------------------------------
// Phase 2: persistent recurrence, fp16 MMA (m16n8k16), fp32 accum/state.
// (R14 structure; R15 = critical-path latency diet: tanh.approx gate math +
//  nanosleep-free acquire poll. Everything else identical.)
// 128 CTAs (1/SM), 512 threads (16 warps). Warp w = (kh=w>>1, mh=w&1).
// ---------------------------------------------------------------------------
__global__ void __launch_bounds__(512,1) lstm_rec(
    const float* __restrict__ Wh1,const float* __restrict__ Wh2,
    const float* __restrict__ Wh3,const float* __restrict__ Wh4,
    float* __restrict__ out)
{
  extern __shared__ float sm[];
  float4* red4 = (float4*)sm;             // 2 x 2048 float4 (64KB): kh partials
  uint4*  Bp4  = (uint4*)(sm + 16384);    // 4096 uint4 (64KB): packed fp16 B frags

  const int tid=threadIdx.x, w=tid>>5, lane=tid&31;
  const int g=lane>>2, tg=lane&3, cta=blockIdx.x;
  const int kh=w>>1, mh=w&1;

  { // one-time fp16 B pack: Bp4[(j*2+p)*32+lane] = {b0,b1 of gate 2p, b0,b1 of 2p+1}
    const float* Whs[4]={Wh1,Wh2,Wh3,Wh4};
    for(int idx=tid; idx<4096; idx+=512){
      int ln=idx&31, p=(idx>>5)&1, j=idx>>6;
      int g_=ln>>2, tg_=ln&3;
      int col=8*cta+g_;
      int k0=16*j+2*tg_;
      uint4 val;
      const float* W0=Whs[2*p];
      const float* W1=Whs[2*p+1];
      val.x=packh2(W0[(size_t)k0*NH+col],     W0[(size_t)(k0+1)*NH+col]);
      val.y=packh2(W0[(size_t)(k0+8)*NH+col], W0[(size_t)(k0+9)*NH+col]);
      val.z=packh2(W1[(size_t)k0*NH+col],     W1[(size_t)(k0+1)*NH+col]);
      val.w=packh2(W1[(size_t)(k0+8)*NH+col], W1[(size_t)(k0+9)*NH+col]);
      Bp4[(j*2+p)*32+ln]=val;
    }
  }
  __syncthreads();

  unsigned* myArr = g_flags + (cta>>4)*SQ;   // producer arrival row (16-CTA group)
  unsigned* myPol = g_flags + kh*SQ;         // consumer poll row (slab kh)
  float cst[4]={0,0,0,0}, hv[4]={0,0,0,0};

  #pragma unroll 1
  for(int t=0;t<SQ;t++){
    // xg loads: independent of h -> issue before any waiting (epilogue warps)
    float2 xr[8];
    if(w<4){
      const float* xb = g_xg + ((size_t)t*NB + 16*w + g)*NG + 8*cta + 2*tg;
      #pragma unroll
      for(int nt=0;nt<4;nt++){
        xr[nt]   = __ldcg((const float2*)(xb + nt*NH));
        xr[4+nt] = __ldcg((const float2*)(xb + (size_t)8*NG + nt*NH));
      }
    }

    float acc[2][4][4];
    #pragma unroll
    for(int i=0;i<2;i++)
      #pragma unroll
      for(int n=0;n<4;n++)
        #pragma unroll
        for(int e=0;e<4;e++) acc[i][n][e]=0.f;

    if(t>0){
      { // tight per-warp acquire poll on this slab's producer group
        const unsigned* fp = myPol + (t-1);
        unsigned v;
        do {
          asm volatile("ld.acquire.gpu.global.u32 %0, [%1];" : "=r"(v) : "l"(fp) : "memory");
        } while(v < 64u);
      }
      const uint4* fb = g_hfrag + (size_t)(t-1)*8192;
      uint4 A[2][2];
      { int j=kh*8;
        A[0][0]=__ldcg(fb + ((j*4 + 2*mh+0)*32+lane));
        A[0][1]=__ldcg(fb + ((j*4 + 2*mh+1)*32+lane));
      }
      #pragma unroll
      for(int jj=0;jj<8;jj++){
        int cur=jj&1, nxt=cur^1;
        int j=kh*8+jj;
        if(jj<7){
          A[nxt][0]=__ldcg(fb + (((j+1)*4 + 2*mh+0)*32+lane));
          A[nxt][1]=__ldcg(fb + (((j+1)*4 + 2*mh+1)*32+lane));
        }
        uint4 B0=Bp4[(j*2+0)*32+lane];
        uint4 B1=Bp4[(j*2+1)*32+lane];
        #pragma unroll
        for(int i=0;i<2;i++){
          mma16(acc[i][0],A[cur][i].x,A[cur][i].y,A[cur][i].z,A[cur][i].w,B0.x,B0.y);
          mma16(acc[i][1],A[cur][i].x,A[cur][i].y,A[cur][i].z,A[cur][i].w,B0.z,B0.w);
          mma16(acc[i][2],A[cur][i].x,A[cur][i].y,A[cur][i].z,A[cur][i].w,B1.x,B1.y);
          mma16(acc[i][3],A[cur][i].x,A[cur][i].y,A[cur][i].z,A[cur][i].w,B1.z,B1.w);
        }
      }
    }

    // 2-phase kh reduction. slot s = (kh mod 4)*2 + mh.
    float4* rb = red4 + (t&1)*2048;
    if(w>=8){                             // phase A: kh 4..7 write slots
      int s=(kh-4)*2+mh;
      #pragma unroll
      for(int i=0;i<2;i++)
        #pragma unroll
        for(int n=0;n<4;n++)
          rb[((s*8 + i*4+n)*32+lane)] =
            make_float4(acc[i][n][0],acc[i][n][1],acc[i][n][2],acc[i][n][3]);
    }
    __syncthreads();                      // barrier 1: slots written
    if(w<8){                              // phase B: kh 0..3 add in place
      int s=kh*2+mh;
      #pragma unroll
      for(int i=0;i<2;i++)
        #pragma unroll
        for(int n=0;n<4;n++){
          float4 u=rb[((s*8 + i*4+n)*32+lane)];
          u.x+=acc[i][n][0]; u.y+=acc[i][n][1]; u.z+=acc[i][n][2]; u.w+=acc[i][n][3];
          rb[((s*8 + i*4+n)*32+lane)]=u;
        }
    }
    __syncthreads();                      // barrier 2: folded slots ready
    if(w<4){                              // epilogue: warp w owns mt=w rows
      int mhE=w>>1, ih=w&1;
      float ga[4][4];
      #pragma unroll
      for(int n=0;n<4;n++)
        #pragma unroll
        for(int e=0;e<4;e++) ga[n][e]=0.f;
      #pragma unroll
      for(int k2=0;k2<4;k2++){            // sum 4 folded kh' slots
        int s=k2*2+mhE;
        #pragma unroll
        for(int n=0;n<4;n++){
          float4 u=rb[((s*8 + ih*4+n)*32+lane)];
          ga[n][0]+=u.x; ga[n][1]+=u.y; ga[n][2]+=u.z; ga[n][3]+=u.w;
        }
      }
      // gates: nt order = f,i,o,cand; e: 0=(r0,c0) 1=(r0,c1) 2=(r1,c0) 3=(r1,c1)
      float gv[4][4];
      #pragma unroll
      for(int n=0;n<4;n++){
        gv[n][0]=ga[n][0]+xr[n].x;   gv[n][1]=ga[n][1]+xr[n].y;
        gv[n][2]=ga[n][2]+xr[4+n].x; gv[n][3]=ga[n][3]+xr[4+n].y;
      }
      #pragma unroll
      for(int e=0;e<4;e++){
        float f=sigfa(gv[0][e]), ii=sigfa(gv[1][e]);
        float o=sigfa(gv[2][e]), cd=tanha(gv[3][e]);
        cst[e]=f*cst[e]+ii*cd;
        hv[e]=o*tanha(cst[e]);
      }
      // fragment store FIRST (cross-CTA dependency), then arrive
      unsigned p0=packh2(hv[0],hv[1]), p1=packh2(hv[2],hv[3]);
      uint2* fw = ((uint2*)(g_hfrag + (size_t)t*8192))
                  + (((cta>>1)*4 + w)*32 + lane)*2 + (cta&1);
      *fw = make_uint2(p0,p1);
      __syncwarp();                       // intra-warp ordering of frag STGs
      if(lane==0){                        // cumulative release arrival (+1)
        unsigned* fp = myArr + t;
        asm volatile("red.release.gpu.global.add.u32 [%0], %1;"
                     :: "l"(fp), "r"(1u) : "memory");
      }
      // h_seq output store (fp32), off the release path
      float* hw = out + ((size_t)t*NB + 16*w + g)*NH + 8*cta + 2*tg;
      *(float2*)hw                = make_float2(hv[0],hv[1]);
      *(float2*)(hw+(size_t)8*NH) = make_float2(hv[2],hv[3]);
    }
  }

  if(w<4){  // tails: h_final (== h_seq[511]) then c_final
    float* ho = out + HSEQ + (size_t)(16*w+g)*NH + 8*cta + 2*tg;
    float* co = ho + (size_t)NB*NH;
    *(float2*)ho                = make_float2(hv[0],hv[1]);
    *(float2*)(ho+(size_t)8*NH) = make_float2(hv[2],hv[3]);
    *(float2*)co                = make_float2(cst[0],cst[1]);
    *(float2*)(co+(size_t)8*NH) = make_float2(cst[2],cst[3]);
  }
}

extern "C" void kernel_launch(void* const* d_in, const int* in_sizes, int n_in,
                              void* d_out, int out_size){
  const float* x =(const float*)d_in[0];
  const float* W1=(const float*)d_in[1];  const float* b1=(const float*)d_in[2];
  const float* W2=(const float*)d_in[3];  const float* b2=(const float*)d_in[4];
  const float* W3=(const float*)d_in[5];  const float* b3=(const float*)d_in[6];
  const float* W4=(const float*)d_in[7];  const float* b4=(const float*)d_in[8];
  const float* W5=(const float*)d_in[9];  const float* b5=(const float*)d_in[10];
  const float* W6=(const float*)d_in[11]; const float* b6=(const float*)d_in[12];
  const float* W7=(const float*)d_in[13]; const float* b7=(const float*)d_in[14];
  const float* W8=(const float*)d_in[15]; const float* b8=(const float*)d_in[16];
  float* out=(float*)d_out;

  cudaFuncSetAttribute(xg_gemm,  cudaFuncAttributeMaxDynamicSharedMemorySize, 55296);
  cudaFuncSetAttribute(lstm_rec, cudaFuncAttributeMaxDynamicSharedMemorySize, 131072);

  dim3 grid(32,128);
  xg_gemm<<<grid,512,55296>>>(x, W1,W3,W5,W7, b1,b3,b5,b7, b2,b4,b6,b8);
  lstm_rec<<<128,512,131072>>>(W2,W4,W6,W8, out);
}

// round 17
// speedup vs baseline: 2.1874x; 1.2666x over previous
#include <cuda_runtime.h>
#include <cuda_fp16.h>
#include <cstdint>

#define SQ 512
#define NB 64
#define NH 1024
#define NI 256
#define NG 4096
#define HSEQ ((size_t)SQ*NB*NH)

// scratch (no allocations allowed)
__device__ uint4    g_hfrag[(size_t)SQ*8192]; // h in fp16 A-fragment order, 64MB
__device__ uint4    g_xfrag[(size_t)SQ*2048]; // x in fp16 A-fragment order, 16MB
__device__ unsigned g_flags[8*SQ];            // per-(group,step) arrival counters

__device__ __forceinline__ void mma16(float d[4], unsigned a0,unsigned a1,unsigned a2,unsigned a3,
                                      unsigned b0,unsigned b1){
  asm("mma.sync.aligned.m16n8k16.row.col.f32.f16.f16.f32 "
      "{%0,%1,%2,%3},{%4,%5,%6,%7},{%8,%9},{%0,%1,%2,%3};"
      : "+f"(d[0]),"+f"(d[1]),"+f"(d[2]),"+f"(d[3])
      : "r"(a0),"r"(a1),"r"(a2),"r"(a3),"r"(b0),"r"(b1));
}
__device__ __forceinline__ unsigned packh2(float lo, float hi){
  __half2 h = __floats2half2_rn(lo, hi);
  return *reinterpret_cast<unsigned*>(&h);
}
// fast gate math: tanh.approx (sm_75+), sigmoid via tanh identity
__device__ __forceinline__ float tanha(float x){
  float y; asm("tanh.approx.f32 %0, %1;" : "=f"(y) : "f"(x)); return y;
}
__device__ __forceinline__ float sigfa(float x){ return fmaf(0.5f, tanha(0.5f*x), 0.5f); }

// ---------------------------------------------------------------------------
// x_pack: x (S,B,I) fp32 -> g_xfrag fp16 A-fragments, layout
// [t][jp(16)][mt(4)][lane] uint4 = {a0,a1,a2,a3} for m16n8k16, identical to
// the h-fragment convention (a0: row 16mt+g cols 16jp+2tg..+1; a1: row+8;
// a2/a3: cols+8). Block 0 also resets the recurrence flags (kernel completes
// before lstm_rec on the same stream).
// ---------------------------------------------------------------------------
__global__ void __launch_bounds__(512) x_pack(const float* __restrict__ x){
  const int t = blockIdx.x;
  if(t==0){
    for(int p=threadIdx.x; p<8*SQ; p+=512) g_flags[p]=0u;
  }
  const float* xb = x + (size_t)t*NB*NI;
  uint4* ob = g_xfrag + (size_t)t*2048;
  for(int idx=threadIdx.x; idx<2048; idx+=512){
    int lane=idx&31, mt=(idx>>5)&3, jp=idx>>7;
    int g_=lane>>2, tg_=lane&3;
    int r0=16*mt+g_, c0=16*jp+2*tg_;
    float2 u00=*(const float2*)(xb + (size_t)r0*NI + c0);
    float2 u10=*(const float2*)(xb + (size_t)(r0+8)*NI + c0);
    float2 u01=*(const float2*)(xb + (size_t)r0*NI + c0+8);
    float2 u11=*(const float2*)(xb + (size_t)(r0+8)*NI + c0+8);
    uint4 v;
    v.x=packh2(u00.x,u00.y); v.y=packh2(u10.x,u10.y);
    v.z=packh2(u01.x,u01.y); v.w=packh2(u11.x,u11.y);
    ob[idx]=v;
  }
}

// ---------------------------------------------------------------------------
// Fused persistent LSTM: per step, gates = h(t-1)@Wh + x(t)@Wx + bx + bh,
// all in fp16 MMA (m16n8k16) with fp32 accum/state.
// 128 CTAs (1/SM), 512 threads (16 warps). CTA c owns h-cols [8c,8c+8) and
// the matching 8 cols of all 4 gates. Warp w = (kh=w>>1, mh=w&1).
//  - x-side: warp kh handles x-chunks jp=2kh,2kh+1 (K=256 over 16 chunks),
//    issued BEFORE the poll -> fills the producer-wait window. No sync needed
//    (g_xfrag precomputed).
//  - h-side: slab j in [8kh,8kh+8) (K=1024), fragment loads straight from
//    g_hfrag after the group flag acquire. Same machinery as R15.
//  - Wh B-frags (64KB) + Wx B-frags (16KB) + bias (32 floats) packed in smem
//    once. 2-phase kh reduction (2x32KB parity), 2 barriers/step.
//  - sync: 8 producer groups of 16 CTAs; 4 epilogue warps arrive via
//    red.release.gpu.add (target 64); consumer polls with tight ld.acquire.
//    Poll (<64): stale-safe under ncu replay.
// ---------------------------------------------------------------------------
__global__ void __launch_bounds__(512,1) lstm_rec(
    const float* __restrict__ Wh1,const float* __restrict__ Wh2,
    const float* __restrict__ Wh3,const float* __restrict__ Wh4,
    const float* __restrict__ Wx1,const float* __restrict__ Wx2,
    const float* __restrict__ Wx3,const float* __restrict__ Wx4,
    const float* __restrict__ bx1,const float* __restrict__ bx2,
    const float* __restrict__ bx3,const float* __restrict__ bx4,
    const float* __restrict__ bh1,const float* __restrict__ bh2,
    const float* __restrict__ bh3,const float* __restrict__ bh4,
    float* __restrict__ out)
{
  extern __shared__ float sm[];
  float4* red4  = (float4*)sm;            // 2 x 2048 float4 (64KB): kh partials
  uint4*  Bp4   = (uint4*)(sm + 16384);   // 4096 uint4 (64KB): Wh fp16 B frags
  uint4*  XBp4  = (uint4*)(sm + 32768);   // 1024 uint4 (16KB): Wx fp16 B frags
  float*  biasS = sm + 36864;             // 32 floats: bx+bh for this CTA

  const int tid=threadIdx.x, w=tid>>5, lane=tid&31;
  const int g=lane>>2, tg=lane&3, cta=blockIdx.x;
  const int kh=w>>1, mh=w&1;

  { // one-time Wh pack: Bp4[(j*2+p)*32+ln] = {b0,b1 of gate 2p, b0,b1 of 2p+1}
    const float* Whs[4]={Wh1,Wh2,Wh3,Wh4};
    for(int idx=tid; idx<4096; idx+=512){
      int ln=idx&31, p=(idx>>5)&1, j=idx>>6;
      int g_=ln>>2, tg_=ln&3;
      int col=8*cta+g_;
      int k0=16*j+2*tg_;
      uint4 val;
      const float* W0=Whs[2*p];
      const float* W1=Whs[2*p+1];
      val.x=packh2(W0[(size_t)k0*NH+col],     W0[(size_t)(k0+1)*NH+col]);
      val.y=packh2(W0[(size_t)(k0+8)*NH+col], W0[(size_t)(k0+9)*NH+col]);
      val.z=packh2(W1[(size_t)k0*NH+col],     W1[(size_t)(k0+1)*NH+col]);
      val.w=packh2(W1[(size_t)(k0+8)*NH+col], W1[(size_t)(k0+9)*NH+col]);
      Bp4[(j*2+p)*32+ln]=val;
    }
  }
  { // one-time Wx pack (K=256, 16 chunks), same fragment convention
    const float* Wxs[4]={Wx1,Wx2,Wx3,Wx4};
    for(int idx=tid; idx<1024; idx+=512){
      int ln=idx&31, p=(idx>>5)&1, jp=idx>>6;
      int g_=ln>>2, tg_=ln&3;
      int col=8*cta+g_;
      int k0=16*jp+2*tg_;
      uint4 val;
      const float* W0=Wxs[2*p];
      const float* W1=Wxs[2*p+1];
      val.x=packh2(W0[(size_t)k0*NH+col],     W0[(size_t)(k0+1)*NH+col]);
      val.y=packh2(W0[(size_t)(k0+8)*NH+col], W0[(size_t)(k0+9)*NH+col]);
      val.z=packh2(W1[(size_t)k0*NH+col],     W1[(size_t)(k0+1)*NH+col]);
      val.w=packh2(W1[(size_t)(k0+8)*NH+col], W1[(size_t)(k0+9)*NH+col]);
      XBp4[(jp*2+p)*32+ln]=val;
    }
  }
  if(tid<32){  // combined bias: biasS[nt*8+cc], gate order f,i,o,cand
    int nt=tid>>3, cc=tid&7, col=8*cta+cc;
    const float* bxs[4]={bx1,bx2,bx3,bx4};
    const float* bhs[4]={bh1,bh2,bh3,bh4};
    biasS[tid]=bxs[nt][col]+bhs[nt][col];
  }
  __syncthreads();

  // epilogue bias registers (warps 0-3): cols 2tg,2tg+1 of each gate
  float bb[4][2];
  if(w<4){
    #pragma unroll
    for(int n=0;n<4;n++){ bb[n][0]=biasS[n*8+2*tg]; bb[n][1]=biasS[n*8+2*tg+1]; }
  }

  unsigned* myArr = g_flags + (cta>>4)*SQ;   // producer arrival row (16-CTA group)
  unsigned* myPol = g_flags + kh*SQ;         // consumer poll row (slab kh)
  float cst[4]={0,0,0,0}, hv[4]={0,0,0,0};

  #pragma unroll 1
  for(int t=0;t<SQ;t++){
    float acc[2][4][4];
    #pragma unroll
    for(int i=0;i<2;i++)
      #pragma unroll
      for(int n=0;n<4;n++)
        #pragma unroll
        for(int e=0;e<4;e++) acc[i][n][e]=0.f;

    { // x-side MMA first: independent of h -> fills the producer-wait window
      const uint4* fx = g_xfrag + (size_t)t*2048;
      #pragma unroll
      for(int q=0;q<2;q++){
        int jp=2*kh+q;
        uint4 A0=__ldcg(fx + ((jp*4 + 2*mh+0)*32+lane));
        uint4 A1=__ldcg(fx + ((jp*4 + 2*mh+1)*32+lane));
        uint4 B0=XBp4[(jp*2+0)*32+lane];
        uint4 B1=XBp4[(jp*2+1)*32+lane];
        mma16(acc[0][0],A0.x,A0.y,A0.z,A0.w,B0.x,B0.y);
        mma16(acc[0][1],A0.x,A0.y,A0.z,A0.w,B0.z,B0.w);
        mma16(acc[0][2],A0.x,A0.y,A0.z,A0.w,B1.x,B1.y);
        mma16(acc[0][3],A0.x,A0.y,A0.z,A0.w,B1.z,B1.w);
        mma16(acc[1][0],A1.x,A1.y,A1.z,A1.w,B0.x,B0.y);
        mma16(acc[1][1],A1.x,A1.y,A1.z,A1.w,B0.z,B0.w);
        mma16(acc[1][2],A1.x,A1.y,A1.z,A1.w,B1.x,B1.y);
        mma16(acc[1][3],A1.x,A1.y,A1.z,A1.w,B1.z,B1.w);
      }
    }

    if(t>0){
      { // tight per-warp acquire poll on this slab's producer group
        const unsigned* fp = myPol + (t-1);
        unsigned v;
        do {
          asm volatile("ld.acquire.gpu.global.u32 %0, [%1];" : "=r"(v) : "l"(fp) : "memory");
        } while(v < 64u);
      }
      const uint4* fb = g_hfrag + (size_t)(t-1)*8192;
      uint4 A[2][2];
      { int j=kh*8;
        A[0][0]=__ldcg(fb + ((j*4 + 2*mh+0)*32+lane));
        A[0][1]=__ldcg(fb + ((j*4 + 2*mh+1)*32+lane));
      }
      #pragma unroll
      for(int jj=0;jj<8;jj++){
        int cur=jj&1, nxt=cur^1;
        int j=kh*8+jj;
        if(jj<7){
          A[nxt][0]=__ldcg(fb + (((j+1)*4 + 2*mh+0)*32+lane));
          A[nxt][1]=__ldcg(fb + (((j+1)*4 + 2*mh+1)*32+lane));
        }
        uint4 B0=Bp4[(j*2+0)*32+lane];
        uint4 B1=Bp4[(j*2+1)*32+lane];
        #pragma unroll
        for(int i=0;i<2;i++){
          mma16(acc[i][0],A[cur][i].x,A[cur][i].y,A[cur][i].z,A[cur][i].w,B0.x,B0.y);
          mma16(acc[i][1],A[cur][i].x,A[cur][i].y,A[cur][i].z,A[cur][i].w,B0.z,B0.w);
          mma16(acc[i][2],A[cur][i].x,A[cur][i].y,A[cur][i].z,A[cur][i].w,B1.x,B1.y);
          mma16(acc[i][3],A[cur][i].x,A[cur][i].y,A[cur][i].z,A[cur][i].w,B1.z,B1.w);
        }
      }
    }

    // 2-phase kh reduction. slot s = (kh mod 4)*2 + mh.
    float4* rb = red4 + (t&1)*2048;
    if(w>=8){                             // phase A: kh 4..7 write slots
      int s=(kh-4)*2+mh;
      #pragma unroll
      for(int i=0;i<2;i++)
        #pragma unroll
        for(int n=0;n<4;n++)
          rb[((s*8 + i*4+n)*32+lane)] =
            make_float4(acc[i][n][0],acc[i][n][1],acc[i][n][2],acc[i][n][3]);
    }
    __syncthreads();                      // barrier 1: slots written
    if(w<8){                              // phase B: kh 0..3 add in place
      int s=kh*2+mh;
      #pragma unroll
      for(int i=0;i<2;i++)
        #pragma unroll
        for(int n=0;n<4;n++){
          float4 u=rb[((s*8 + i*4+n)*32+lane)];
          u.x+=acc[i][n][0]; u.y+=acc[i][n][1]; u.z+=acc[i][n][2]; u.w+=acc[i][n][3];
          rb[((s*8 + i*4+n)*32+lane)]=u;
        }
    }
    __syncthreads();                      // barrier 2: folded slots ready
    if(w<4){                              // epilogue: warp w owns mt=w rows
      int mhE=w>>1, ih=w&1;
      float ga[4][4];
      #pragma unroll
      for(int n=0;n<4;n++)
        #pragma unroll
        for(int e=0;e<4;e++) ga[n][e]=0.f;
      #pragma unroll
      for(int k2=0;k2<4;k2++){            // sum 4 folded kh' slots
        int s=k2*2+mhE;
        #pragma unroll
        for(int n=0;n<4;n++){
          float4 u=rb[((s*8 + ih*4+n)*32+lane)];
          ga[n][0]+=u.x; ga[n][1]+=u.y; ga[n][2]+=u.z; ga[n][3]+=u.w;
        }
      }
      // gates: nt order = f,i,o,cand; e: 0=(r0,c0) 1=(r0,c1) 2=(r1,c0) 3=(r1,c1)
      float gv[4][4];
      #pragma unroll
      for(int n=0;n<4;n++){
        gv[n][0]=ga[n][0]+bb[n][0]; gv[n][1]=ga[n][1]+bb[n][1];
        gv[n][2]=ga[n][2]+bb[n][0]; gv[n][3]=ga[n][3]+bb[n][1];
      }
      #pragma unroll
      for(int e=0;e<4;e++){
        float f=sigfa(gv[0][e]), ii=sigfa(gv[1][e]);
        float o=sigfa(gv[2][e]), cd=tanha(gv[3][e]);
        cst[e]=f*cst[e]+ii*cd;
        hv[e]=o*tanha(cst[e]);
      }
      // fragment store FIRST (cross-CTA dependency), then arrive
      unsigned p0=packh2(hv[0],hv[1]), p1=packh2(hv[2],hv[3]);
      uint2* fw = ((uint2*)(g_hfrag + (size_t)t*8192))
                  + (((cta>>1)*4 + w)*32 + lane)*2 + (cta&1);
      *fw = make_uint2(p0,p1);
      __syncwarp();                       // intra-warp ordering of frag STGs
      if(lane==0){                        // cumulative release arrival (+1)
        unsigned* fp = myArr + t;
        asm volatile("red.release.gpu.global.add.u32 [%0], %1;"
                     :: "l"(fp), "r"(1u) : "memory");
      }
      // h_seq output store (fp32), off the release path
      float* hw = out + ((size_t)t*NB + 16*w + g)*NH + 8*cta + 2*tg;
      *(float2*)hw                = make_float2(hv[0],hv[1]);
      *(float2*)(hw+(size_t)8*NH) = make_float2(hv[2],hv[3]);
    }
  }

  if(w<4){  // tails: h_final (== h_seq[511]) then c_final
    float* ho = out + HSEQ + (size_t)(16*w+g)*NH + 8*cta + 2*tg;
    float* co = ho + (size_t)NB*NH;
    *(float2*)ho                = make_float2(hv[0],hv[1]);
    *(float2*)(ho+(size_t)8*NH) = make_float2(hv[2],hv[3]);
    *(float2*)co                = make_float2(cst[0],cst[1]);
    *(float2*)(co+(size_t)8*NH) = make_float2(cst[2],cst[3]);
  }
}

extern "C" void kernel_launch(void* const* d_in, const int* in_sizes, int n_in,
                              void* d_out, int out_size){
  const float* x =(const float*)d_in[0];
  const float* W1=(const float*)d_in[1];  const float* b1=(const float*)d_in[2];
  const float* W2=(const float*)d_in[3];  const float* b2=(const float*)d_in[4];
  const float* W3=(const float*)d_in[5];  const float* b3=(const float*)d_in[6];
  const float* W4=(const float*)d_in[7];  const float* b4=(const float*)d_in[8];
  const float* W5=(const float*)d_in[9];  const float* b5=(const float*)d_in[10];
  const float* W6=(const float*)d_in[11]; const float* b6=(const float*)d_in[12];
  const float* W7=(const float*)d_in[13]; const float* b7=(const float*)d_in[14];
  const float* W8=(const float*)d_in[15]; const float* b8=(const float*)d_in[16];
  float* out=(float*)d_out;

  cudaFuncSetAttribute(lstm_rec, cudaFuncAttributeMaxDynamicSharedMemorySize, 147584);

  x_pack<<<512,512>>>(x);
  lstm_rec<<<128,512,147584>>>(W2,W4,W6,W8,      // Wh: gates f,i,o,cand
                               W1,W3,W5,W7,      // Wx
                               b1,b3,b5,b7,      // bx
                               b2,b4,b6,b8,      // bh
                               out);
}